// round 1
// baseline (speedup 1.0000x reference)
#include <cuda_runtime.h>
#include <cuda_bf16.h>
#include <math.h>

// Problem constants
#define BB 2
#define SS 4096
#define DD 768
#define HH 12
#define DHH 64
#define DFF 3072
#define MM (BB*SS)   // 8192

// ---------------------------------------------------------------------------
// Scratch (device globals — allocation-free per harness rules)
// ---------------------------------------------------------------------------
__device__ float g_l1[MM*DD];
__device__ float g_q [MM*DD];
__device__ float g_k [MM*DD];
__device__ float g_v [MM*DD];
__device__ float g_x1[MM*DD];
__device__ float g_l2[MM*DD];
__device__ float g_hb[MM*DFF];

// ---------------------------------------------------------------------------
// LayerNorm: torch-style, unbiased std (ddof=1), normalizer = (sigma + eps)
// One block per row, 256 threads, 3 elements/thread (D=768).
// ---------------------------------------------------------------------------
__global__ void ln_kernel(const float* __restrict__ x,
                          const float* __restrict__ gamma,
                          const float* __restrict__ beta,
                          float* __restrict__ out)
{
    const int row = blockIdx.x;
    const float* xr = x + (long)row * DD;
    float* orow = out + (long)row * DD;

    float vals[3];
    float s = 0.f, ss = 0.f;
#pragma unroll
    for (int t = 0; t < 3; t++) {
        float v = xr[threadIdx.x + t * 256];
        vals[t] = v;
        s += v; ss += v * v;
    }
#pragma unroll
    for (int o = 16; o > 0; o >>= 1) {
        s  += __shfl_xor_sync(0xffffffffu, s,  o);
        ss += __shfl_xor_sync(0xffffffffu, ss, o);
    }
    __shared__ float sw[8], ssw[8];
    __shared__ float mu_s, inv_s;
    const int warp = threadIdx.x >> 5, lane = threadIdx.x & 31;
    if (lane == 0) { sw[warp] = s; ssw[warp] = ss; }
    __syncthreads();
    if (threadIdx.x == 0) {
        float ts = 0.f, tss = 0.f;
#pragma unroll
        for (int i = 0; i < 8; i++) { ts += sw[i]; tss += ssw[i]; }
        float mu  = ts / 768.f;
        float var = fmaxf((tss - 768.f * mu * mu) / 767.f, 0.f);
        mu_s  = mu;
        inv_s = 1.f / (sqrtf(var) + 1e-6f);
    }
    __syncthreads();
    const float mu = mu_s, inv = inv_s;
#pragma unroll
    for (int t = 0; t < 3; t++) {
        int c = threadIdx.x + t * 256;
        orow[c] = gamma[c] * (vals[t] - mu) * inv + beta[c];
    }
}

// ---------------------------------------------------------------------------
// SGEMM: C[M,N] = A[M,K] @ B[K,N] + bias (+ relu | + residual)
// 128x128 block tile, BK=8, 256 threads, 8x8 per-thread microtile.
// EPI: 0 = bias, 1 = bias+relu, 2 = bias+residual
// ---------------------------------------------------------------------------
template<int EPI>
__global__ __launch_bounds__(256)
void sgemm_kernel(const float* __restrict__ A, const float* __restrict__ Bm,
                  const float* __restrict__ bias, const float* __restrict__ res,
                  float* __restrict__ C, int M, int N, int Kdim)
{
    __shared__ float As[8][128];
    __shared__ float Bs[8][128];

    const int tid = threadIdx.x;
    const int tx = tid & 15, ty = tid >> 4;
    const int row0 = blockIdx.y * 128, col0 = blockIdx.x * 128;

    const int arow = tid >> 1, acol = (tid & 1) * 4;
    const int brow = tid >> 5, bcol = (tid & 31) * 4;

    const float* Aptr = A  + (long)(row0 + arow) * Kdim + acol;
    const float* Bptr = Bm + (long)brow * N + col0 + bcol;

    float acc[8][8] = {};

    for (int kt = 0; kt < Kdim; kt += 8) {
        float4 av = *(const float4*)(Aptr + kt);
        float4 bv = *(const float4*)(Bptr + (long)kt * N);
        As[acol + 0][arow] = av.x;
        As[acol + 1][arow] = av.y;
        As[acol + 2][arow] = av.z;
        As[acol + 3][arow] = av.w;
        *(float4*)&Bs[brow][bcol] = bv;
        __syncthreads();
#pragma unroll
        for (int kk = 0; kk < 8; kk++) {
            float a[8], b[8];
            float4 a0 = *(const float4*)&As[kk][ty * 8];
            float4 a1 = *(const float4*)&As[kk][ty * 8 + 4];
            float4 b0 = *(const float4*)&Bs[kk][tx * 8];
            float4 b1 = *(const float4*)&Bs[kk][tx * 8 + 4];
            a[0]=a0.x; a[1]=a0.y; a[2]=a0.z; a[3]=a0.w;
            a[4]=a1.x; a[5]=a1.y; a[6]=a1.z; a[7]=a1.w;
            b[0]=b0.x; b[1]=b0.y; b[2]=b0.z; b[3]=b0.w;
            b[4]=b1.x; b[5]=b1.y; b[6]=b1.z; b[7]=b1.w;
#pragma unroll
            for (int i = 0; i < 8; i++)
#pragma unroll
                for (int j = 0; j < 8; j++)
                    acc[i][j] += a[i] * b[j];
        }
        __syncthreads();
    }

#pragma unroll
    for (int i = 0; i < 8; i++) {
        const long crow = row0 + ty * 8 + i;
#pragma unroll
        for (int j = 0; j < 8; j++) {
            const int ccol = col0 + tx * 8 + j;
            float v = acc[i][j] + bias[ccol];
            if (EPI == 1) v = fmaxf(v, 0.f);
            if (EPI == 2) v += res[crow * N + ccol];
            C[crow * N + ccol] = v;
        }
    }
}

// ---------------------------------------------------------------------------
// Flash attention (fp32, streaming softmax, multiplicative pre-softmax mask).
// Q,K,V laid out [B*S, D] (head h occupies columns h*64..h*64+63).
// One block per (q-tile of 64 rows, head, batch). 128 threads; each thread
// owns 2 query rows x 16 key columns (register blocking halves LDS traffic).
// Fuses the residual: x1 = x + ctx.
// ---------------------------------------------------------------------------
#define TP 65   // smem pitch (conflict-free column access)
#define ATTN_SMEM (4 * 64 * TP * (int)sizeof(float))

__global__ __launch_bounds__(128)
void attn_kernel(const float* __restrict__ Q, const float* __restrict__ K,
                 const float* __restrict__ V, const float* __restrict__ mask,
                 const float* __restrict__ x, float* __restrict__ x1)
{
    extern __shared__ float sm[];
    float* Qs = sm;
    float* Ks = sm + 64 * TP;
    float* Vs = sm + 2 * 64 * TP;
    float* Ps = sm + 3 * 64 * TP;

    const int tid = threadIdx.x;
    const int r   = tid >> 2;      // 0..31 (rows r and r+32)
    const int cg  = tid & 3;
    const int c0  = cg * 16;
    const int qb = blockIdx.x, h = blockIdx.y, b = blockIdx.z;
    const int q0 = qb * 64;
    const int hoff = h * 64;

    // stage Q (rows r, r+32; cols c0..c0+15)
    {
        const long base0 = ((long)(b * SS + q0 + r)) * DD + hoff + c0;
        const long base1 = base0 + 32L * DD;
#pragma unroll
        for (int i = 0; i < 16; i += 4) {
            float4 t0 = *(const float4*)(Q + base0 + i);
            float4 t1 = *(const float4*)(Q + base1 + i);
            Qs[r * TP + c0 + i + 0] = t0.x; Qs[r * TP + c0 + i + 1] = t0.y;
            Qs[r * TP + c0 + i + 2] = t0.z; Qs[r * TP + c0 + i + 3] = t0.w;
            Qs[(r+32) * TP + c0 + i + 0] = t1.x; Qs[(r+32) * TP + c0 + i + 1] = t1.y;
            Qs[(r+32) * TP + c0 + i + 2] = t1.z; Qs[(r+32) * TP + c0 + i + 3] = t1.w;
        }
    }

    float O0[16], O1[16];
#pragma unroll
    for (int j = 0; j < 16; j++) { O0[j] = 0.f; O1[j] = 0.f; }
    float m0 = -INFINITY, m1 = -INFINITY, l0 = 0.f, l1 = 0.f;

    const float* mrow0 = mask + ((long)b * SS + q0 + r) * SS;
    const float* mrow1 = mrow0 + 32L * SS;

    for (int kb = 0; kb < SS / 64; kb++) {
        const int k0 = kb * 64;
        // stage K,V tiles
        {
            const long kb0 = ((long)(b * SS + k0 + r)) * DD + hoff + c0;
            const long kb1 = kb0 + 32L * DD;
#pragma unroll
            for (int i = 0; i < 16; i += 4) {
                float4 tk0 = *(const float4*)(K + kb0 + i);
                float4 tk1 = *(const float4*)(K + kb1 + i);
                float4 tv0 = *(const float4*)(V + kb0 + i);
                float4 tv1 = *(const float4*)(V + kb1 + i);
                Ks[r * TP + c0 + i + 0] = tk0.x; Ks[r * TP + c0 + i + 1] = tk0.y;
                Ks[r * TP + c0 + i + 2] = tk0.z; Ks[r * TP + c0 + i + 3] = tk0.w;
                Ks[(r+32) * TP + c0 + i + 0] = tk1.x; Ks[(r+32) * TP + c0 + i + 1] = tk1.y;
                Ks[(r+32) * TP + c0 + i + 2] = tk1.z; Ks[(r+32) * TP + c0 + i + 3] = tk1.w;
                Vs[r * TP + c0 + i + 0] = tv0.x; Vs[r * TP + c0 + i + 1] = tv0.y;
                Vs[r * TP + c0 + i + 2] = tv0.z; Vs[r * TP + c0 + i + 3] = tv0.w;
                Vs[(r+32) * TP + c0 + i + 0] = tv1.x; Vs[(r+32) * TP + c0 + i + 1] = tv1.y;
                Vs[(r+32) * TP + c0 + i + 2] = tv1.z; Vs[(r+32) * TP + c0 + i + 3] = tv1.w;
            }
        }
        __syncthreads();

        // scores: s[rq][c] = sum_d Q[rq][d] * K[c0+c][d]
        float s0[16], s1[16];
#pragma unroll
        for (int c = 0; c < 16; c++) { s0[c] = 0.f; s1[c] = 0.f; }
        for (int d = 0; d < 64; d++) {
            const float q0v = Qs[r * TP + d];
            const float q1v = Qs[(r + 32) * TP + d];
#pragma unroll
            for (int c = 0; c < 16; c++) {
                const float kv = Ks[(c0 + c) * TP + d];
                s0[c] += q0v * kv;
                s1[c] += q1v * kv;
            }
        }
        // scale then multiplicative mask (pre-softmax)
#pragma unroll
        for (int c = 0; c < 16; c += 4) {
            float4 mA = *(const float4*)(mrow0 + k0 + c0 + c);
            float4 mB = *(const float4*)(mrow1 + k0 + c0 + c);
            s0[c+0] *= 0.125f * mA.x; s0[c+1] *= 0.125f * mA.y;
            s0[c+2] *= 0.125f * mA.z; s0[c+3] *= 0.125f * mA.w;
            s1[c+0] *= 0.125f * mB.x; s1[c+1] *= 0.125f * mB.y;
            s1[c+2] *= 0.125f * mB.z; s1[c+3] *= 0.125f * mB.w;
        }

        // streaming softmax (row state shared by the 4 threads of each quad)
        float mx0 = s0[0], mx1 = s1[0];
#pragma unroll
        for (int c = 1; c < 16; c++) { mx0 = fmaxf(mx0, s0[c]); mx1 = fmaxf(mx1, s1[c]); }
        mx0 = fmaxf(mx0, __shfl_xor_sync(0xffffffffu, mx0, 1));
        mx0 = fmaxf(mx0, __shfl_xor_sync(0xffffffffu, mx0, 2));
        mx1 = fmaxf(mx1, __shfl_xor_sync(0xffffffffu, mx1, 1));
        mx1 = fmaxf(mx1, __shfl_xor_sync(0xffffffffu, mx1, 2));
        const float mn0 = fmaxf(m0, mx0), mn1 = fmaxf(m1, mx1);
        const float a0 = __expf(m0 - mn0), a1 = __expf(m1 - mn1);
        float sum0 = 0.f, sum1 = 0.f;
#pragma unroll
        for (int c = 0; c < 16; c++) {
            s0[c] = __expf(s0[c] - mn0); sum0 += s0[c];
            s1[c] = __expf(s1[c] - mn1); sum1 += s1[c];
        }
        sum0 += __shfl_xor_sync(0xffffffffu, sum0, 1);
        sum0 += __shfl_xor_sync(0xffffffffu, sum0, 2);
        sum1 += __shfl_xor_sync(0xffffffffu, sum1, 1);
        sum1 += __shfl_xor_sync(0xffffffffu, sum1, 2);
        l0 = l0 * a0 + sum0; l1 = l1 * a1 + sum1;
        m0 = mn0; m1 = mn1;
#pragma unroll
        for (int j = 0; j < 16; j++) { O0[j] *= a0; O1[j] *= a1; }
#pragma unroll
        for (int c = 0; c < 16; c++) {
            Ps[r * TP + c0 + c] = s0[c];
            Ps[(r + 32) * TP + c0 + c] = s1[c];
        }
        __syncthreads();

        // O += P @ V
        for (int c = 0; c < 64; c++) {
            const float p0 = Ps[r * TP + c];
            const float p1 = Ps[(r + 32) * TP + c];
#pragma unroll
            for (int j = 0; j < 16; j++) {
                const float vv = Vs[c * TP + c0 + j];
                O0[j] += p0 * vv;
                O1[j] += p1 * vv;
            }
        }
        __syncthreads();
    }

    // finalize + fused residual: x1 = x + ctx
    const float inv0 = 1.f / l0, inv1 = 1.f / l1;
    const long o0 = ((long)(b * SS + q0 + r)) * DD + hoff + c0;
    const long o1 = o0 + 32L * DD;
#pragma unroll
    for (int j = 0; j < 16; j++) {
        x1[o0 + j] = x[o0 + j] + O0[j] * inv0;
        x1[o1 + j] = x[o1 + j] + O1[j] * inv1;
    }
}

// ---------------------------------------------------------------------------
// Launch: LN1 -> Q/K/V GEMMs -> flash attn (+residual) -> LN2 -> FFN1(relu)
//         -> FFN2 (+bias +residual) -> d_out
// NOTE: reference never applies the output projection (wo/bo unused).
// ---------------------------------------------------------------------------
extern "C" void kernel_launch(void* const* d_in, const int* in_sizes, int n_in,
                              void* d_out, int out_size)
{
    const float* x    = (const float*)d_in[0];
    const float* mask = (const float*)d_in[1];
    const float* wq   = (const float*)d_in[2];
    const float* bq   = (const float*)d_in[3];
    const float* wk   = (const float*)d_in[4];
    const float* bk   = (const float*)d_in[5];
    const float* wv   = (const float*)d_in[6];
    const float* bv   = (const float*)d_in[7];
    // d_in[8] = wo, d_in[9] = bo : unused by the reference forward
    const float* w1   = (const float*)d_in[10];
    const float* b1   = (const float*)d_in[11];
    const float* w2   = (const float*)d_in[12];
    const float* b2   = (const float*)d_in[13];
    const float* g1   = (const float*)d_in[14];
    const float* be1  = (const float*)d_in[15];
    const float* g2   = (const float*)d_in[16];
    const float* be2  = (const float*)d_in[17];
    float* out = (float*)d_out;

    float *l1, *qb, *kb, *vb, *x1, *l2, *hb;
    cudaGetSymbolAddress((void**)&l1, g_l1);
    cudaGetSymbolAddress((void**)&qb, g_q);
    cudaGetSymbolAddress((void**)&kb, g_k);
    cudaGetSymbolAddress((void**)&vb, g_v);
    cudaGetSymbolAddress((void**)&x1, g_x1);
    cudaGetSymbolAddress((void**)&l2, g_l2);
    cudaGetSymbolAddress((void**)&hb, g_hb);

    // LN1
    ln_kernel<<<MM, 256>>>(x, g1, be1, l1);

    // QKV projections
    dim3 gproj(DD / 128, MM / 128);   // (6, 64)
    sgemm_kernel<0><<<gproj, 256>>>(l1, wq, bq, nullptr, qb, MM, DD, DD);
    sgemm_kernel<0><<<gproj, 256>>>(l1, wk, bk, nullptr, kb, MM, DD, DD);
    sgemm_kernel<0><<<gproj, 256>>>(l1, wv, bv, nullptr, vb, MM, DD, DD);

    // Flash attention + residual
    cudaFuncSetAttribute(attn_kernel, cudaFuncAttributeMaxDynamicSharedMemorySize, ATTN_SMEM);
    attn_kernel<<<dim3(SS / 64, HH, BB), 128, ATTN_SMEM>>>(qb, kb, vb, mask, x, x1);

    // LN2
    ln_kernel<<<MM, 256>>>(x1, g2, be2, l2);

    // FFN
    sgemm_kernel<1><<<dim3(DFF / 128, MM / 128), 256>>>(l2, w1, b1, nullptr, hb, MM, DFF, DD);
    sgemm_kernel<2><<<dim3(DD / 128, MM / 128), 256>>>(hb, w2, b2, x1, out, MM, DD, DFF);
}

// round 2
// speedup vs baseline: 3.3765x; 3.3765x over previous
#include <cuda_runtime.h>
#include <cuda_bf16.h>
#include <math.h>

// Problem constants
#define BB 2
#define SS 4096
#define DD 768
#define HH 12
#define DHH 64
#define DFF 3072
#define MM (BB*SS)   // 8192

// ---------------------------------------------------------------------------
// Scratch (device globals — allocation-free per harness rules)
// ---------------------------------------------------------------------------
__device__ float g_l1[MM*DD];
__device__ float g_q [MM*DD];
__device__ float g_k [MM*DD];
__device__ float g_v [MM*DD];
__device__ float g_x1[MM*DD];
__device__ float g_l2[MM*DD];
__device__ float g_hb[MM*DFF];

// ---------------------------------------------------------------------------
// tf32 helpers
// ---------------------------------------------------------------------------
__device__ __forceinline__ float f2tf32(float x) {
    unsigned r;
    asm("cvt.rna.tf32.f32 %0, %1;" : "=r"(r) : "f"(x));
    return __uint_as_float(r);
}

__device__ __forceinline__ void mma_tf32(float (&d)[4],
                                         unsigned a0, unsigned a1, unsigned a2, unsigned a3,
                                         unsigned b0, unsigned b1)
{
    asm volatile(
        "mma.sync.aligned.m16n8k8.row.col.f32.tf32.tf32.f32 "
        "{%0,%1,%2,%3}, {%4,%5,%6,%7}, {%8,%9}, {%0,%1,%2,%3};\n"
        : "+f"(d[0]), "+f"(d[1]), "+f"(d[2]), "+f"(d[3])
        : "r"(a0), "r"(a1), "r"(a2), "r"(a3), "r"(b0), "r"(b1));
}

// ---------------------------------------------------------------------------
// LayerNorm: torch-style, unbiased std (ddof=1), normalizer = (sigma + eps)
// ---------------------------------------------------------------------------
__global__ void ln_kernel(const float* __restrict__ x,
                          const float* __restrict__ gamma,
                          const float* __restrict__ beta,
                          float* __restrict__ out)
{
    const int row = blockIdx.x;
    const float* xr = x + (long)row * DD;
    float* orow = out + (long)row * DD;

    float vals[3];
    float s = 0.f, ss = 0.f;
#pragma unroll
    for (int t = 0; t < 3; t++) {
        float v = xr[threadIdx.x + t * 256];
        vals[t] = v;
        s += v; ss += v * v;
    }
#pragma unroll
    for (int o = 16; o > 0; o >>= 1) {
        s  += __shfl_xor_sync(0xffffffffu, s,  o);
        ss += __shfl_xor_sync(0xffffffffu, ss, o);
    }
    __shared__ float sw[8], ssw[8];
    __shared__ float mu_s, inv_s;
    const int warp = threadIdx.x >> 5, lane = threadIdx.x & 31;
    if (lane == 0) { sw[warp] = s; ssw[warp] = ss; }
    __syncthreads();
    if (threadIdx.x == 0) {
        float ts = 0.f, tss = 0.f;
#pragma unroll
        for (int i = 0; i < 8; i++) { ts += sw[i]; tss += ssw[i]; }
        float mu  = ts / 768.f;
        float var = fmaxf((tss - 768.f * mu * mu) / 767.f, 0.f);
        mu_s  = mu;
        inv_s = 1.f / (sqrtf(var) + 1e-6f);
    }
    __syncthreads();
    const float mu = mu_s, inv = inv_s;
#pragma unroll
    for (int t = 0; t < 3; t++) {
        int c = threadIdx.x + t * 256;
        orow[c] = gamma[c] * (vals[t] - mu) * inv + beta[c];
    }
}

// ---------------------------------------------------------------------------
// TF32 tensor-core GEMM: C[M,N] = A[M,K] @ B[K,N] + bias (+relu | +residual)
// Block tile 128x128, BK=16, 256 threads = 8 warps (2x4), warp tile 64x32.
// Double-buffered smem; mma.sync.m16n8k8 tf32.
// EPI: 0 = bias, 1 = bias+relu, 2 = bias+residual
// ---------------------------------------------------------------------------
#define AP 20    // As pitch (floats): (20*g + t) mod 32 distinct -> conflict-free frag loads
#define BP 132   // Bs pitch (floats): (132*t + g) mod 32 = 4t+g distinct

template<int EPI>
__global__ __launch_bounds__(256)
void mma_gemm(const float* __restrict__ A, const float* __restrict__ Bm,
              const float* __restrict__ bias, const float* __restrict__ res,
              float* __restrict__ C, int M, int N, int Kdim)
{
    __shared__ float As[2][128 * AP];
    __shared__ float Bs[2][16 * BP];

    const int tid  = threadIdx.x;
    const int wid  = tid >> 5, lane = tid & 31;
    const int wm   = wid >> 2, wn = wid & 3;      // 2x4 warp grid
    const int g    = lane >> 2, t = lane & 3;
    const int row0 = blockIdx.y * 128, col0 = blockIdx.x * 128;

    // staging mapping
    const int ar = tid >> 1;               // A row 0..127
    const int ac = (tid & 1) * 8;          // A col group (2 float4)
    const int br = tid >> 4;               // B row 0..15
    const int bc = (tid & 15) * 8;         // B col group (2 float4)

    const float* Aptr = A  + (long)(row0 + ar) * Kdim + ac;
    const float* Bptr = Bm + (long)br * N + col0 + bc;

    float acc[4][4][4];
#pragma unroll
    for (int i = 0; i < 4; i++)
#pragma unroll
        for (int j = 0; j < 4; j++)
#pragma unroll
            for (int k = 0; k < 4; k++) acc[i][j][k] = 0.f;

    const int niter = Kdim / 16;

    // prime buffer 0
    {
        float4 a0 = *(const float4*)(Aptr);
        float4 a1 = *(const float4*)(Aptr + 4);
        float4 b0 = *(const float4*)(Bptr);
        float4 b1 = *(const float4*)(Bptr + 4);
        float* as = &As[0][ar * AP + ac];
        as[0]=f2tf32(a0.x); as[1]=f2tf32(a0.y); as[2]=f2tf32(a0.z); as[3]=f2tf32(a0.w);
        as[4]=f2tf32(a1.x); as[5]=f2tf32(a1.y); as[6]=f2tf32(a1.z); as[7]=f2tf32(a1.w);
        float* bs = &Bs[0][br * BP + bc];
        bs[0]=f2tf32(b0.x); bs[1]=f2tf32(b0.y); bs[2]=f2tf32(b0.z); bs[3]=f2tf32(b0.w);
        bs[4]=f2tf32(b1.x); bs[5]=f2tf32(b1.y); bs[6]=f2tf32(b1.z); bs[7]=f2tf32(b1.w);
    }
    __syncthreads();

    for (int it = 0; it < niter; it++) {
        const int buf = it & 1;

        // prefetch next tile into registers (latency hidden by MMA chain below)
        float4 pa0, pa1, pb0, pb1;
        const bool havenext = (it + 1 < niter);
        if (havenext) {
            const long ka = (long)(it + 1) * 16;
            pa0 = *(const float4*)(Aptr + ka);
            pa1 = *(const float4*)(Aptr + ka + 4);
            pb0 = *(const float4*)(Bptr + ka * N);
            pb1 = *(const float4*)(Bptr + ka * N + 4);
        }

        // compute on current buffer
        const float* as = As[buf];
        const float* bs = Bs[buf];
#pragma unroll
        for (int ks = 0; ks < 2; ks++) {
            unsigned af[4][4];
#pragma unroll
            for (int mt = 0; mt < 4; mt++) {
                const int rb = (wm * 64 + mt * 16 + g) * AP + ks * 8 + t;
                af[mt][0] = __float_as_uint(as[rb]);
                af[mt][1] = __float_as_uint(as[rb + 8 * AP]);
                af[mt][2] = __float_as_uint(as[rb + 4]);
                af[mt][3] = __float_as_uint(as[rb + 8 * AP + 4]);
            }
            unsigned bf[4][2];
#pragma unroll
            for (int nt = 0; nt < 4; nt++) {
                const int cb = (ks * 8 + t) * BP + wn * 32 + nt * 8 + g;
                bf[nt][0] = __float_as_uint(bs[cb]);
                bf[nt][1] = __float_as_uint(bs[cb + 4 * BP]);
            }
#pragma unroll
            for (int mt = 0; mt < 4; mt++)
#pragma unroll
                for (int nt = 0; nt < 4; nt++)
                    mma_tf32(acc[mt][nt], af[mt][0], af[mt][1], af[mt][2], af[mt][3],
                             bf[nt][0], bf[nt][1]);
        }

        // store prefetched tile into the other buffer
        if (havenext) {
            float* asn = &As[buf ^ 1][ar * AP + ac];
            asn[0]=f2tf32(pa0.x); asn[1]=f2tf32(pa0.y); asn[2]=f2tf32(pa0.z); asn[3]=f2tf32(pa0.w);
            asn[4]=f2tf32(pa1.x); asn[5]=f2tf32(pa1.y); asn[6]=f2tf32(pa1.z); asn[7]=f2tf32(pa1.w);
            float* bsn = &Bs[buf ^ 1][br * BP + bc];
            bsn[0]=f2tf32(pb0.x); bsn[1]=f2tf32(pb0.y); bsn[2]=f2tf32(pb0.z); bsn[3]=f2tf32(pb0.w);
            bsn[4]=f2tf32(pb1.x); bsn[5]=f2tf32(pb1.y); bsn[6]=f2tf32(pb1.z); bsn[7]=f2tf32(pb1.w);
        }
        __syncthreads();
    }

    // epilogue: c0=C[r][2t], c1=C[r][2t+1], c2=C[r+8][2t], c3=C[r+8][2t+1]
#pragma unroll
    for (int mt = 0; mt < 4; mt++) {
#pragma unroll
        for (int nt = 0; nt < 4; nt++) {
            const int  ccol = col0 + wn * 32 + nt * 8 + 2 * t;
            const long ra   = row0 + wm * 64 + mt * 16 + g;
            const long rb2  = ra + 8;
            const float bx = bias[ccol], by = bias[ccol + 1];
            float v0 = acc[mt][nt][0] + bx;
            float v1 = acc[mt][nt][1] + by;
            float v2 = acc[mt][nt][2] + bx;
            float v3 = acc[mt][nt][3] + by;
            if (EPI == 1) {
                v0 = fmaxf(v0, 0.f); v1 = fmaxf(v1, 0.f);
                v2 = fmaxf(v2, 0.f); v3 = fmaxf(v3, 0.f);
            }
            if (EPI == 2) {
                const float2 r0 = *(const float2*)(res + ra  * N + ccol);
                const float2 r1 = *(const float2*)(res + rb2 * N + ccol);
                v0 += r0.x; v1 += r0.y; v2 += r1.x; v3 += r1.y;
            }
            *(float2*)(C + ra  * N + ccol) = make_float2(v0, v1);
            *(float2*)(C + rb2 * N + ccol) = make_float2(v2, v3);
        }
    }
}

// ---------------------------------------------------------------------------
// Flash attention, tf32 tensor cores.
// Block = 128 threads (4 warps); q-tile 64 rows (warp w owns rows 16w..16w+15),
// k-tile 64. 1/8 scale and log2(e) folded into Q; softmax uses exp2f.
// V staged transposed (Vt[d][key]) for conflict-free B-fragment loads.
// Fuses the residual: x1 = x + ctx.
// ---------------------------------------------------------------------------
#define APT 68   // smem pitch for attention tiles (floats)
#define ATTN_SMEM (4 * 64 * APT * (int)sizeof(float))

__global__ __launch_bounds__(128)
void attn_mma_kernel(const float* __restrict__ Q, const float* __restrict__ K,
                     const float* __restrict__ V, const float* __restrict__ mask,
                     const float* __restrict__ x, float* __restrict__ x1)
{
    extern __shared__ float sm[];
    float* Qs = sm;                   // [64 q rows][64 dh]
    float* Ks = sm + 64 * APT;        // [64 k rows][64 dh]
    float* Vt = sm + 2 * 64 * APT;    // [64 dh][64 k rows]  (transposed)
    float* Ps = sm + 3 * 64 * APT;    // [64 q rows][64 k cols]

    const int tid = threadIdx.x;
    const int w = tid >> 5, lane = tid & 31;
    const int g = lane >> 2, t = lane & 3;
    const int qb = blockIdx.x, h = blockIdx.y, b = blockIdx.z;
    const int q0 = qb * 64, hoff = h * 64;

    // staging mapping: rows sr, sr+32; cols sc..sc+15
    const int sr = tid >> 2;
    const int sc = (tid & 3) * 16;

    const float qscale = 0.125f * 1.4426950408889634f;   // 1/sqrt(64) * log2(e)

    // stage Q once (scaled, tf32-rounded)
    {
        const long b0 = ((long)(b * SS + q0 + sr)) * DD + hoff + sc;
        const long b1 = b0 + 32L * DD;
#pragma unroll
        for (int i = 0; i < 16; i += 4) {
            float4 q0v = *(const float4*)(Q + b0 + i);
            float4 q1v = *(const float4*)(Q + b1 + i);
            *(float4*)&Qs[sr * APT + sc + i] = make_float4(
                f2tf32(q0v.x * qscale), f2tf32(q0v.y * qscale),
                f2tf32(q0v.z * qscale), f2tf32(q0v.w * qscale));
            *(float4*)&Qs[(sr + 32) * APT + sc + i] = make_float4(
                f2tf32(q1v.x * qscale), f2tf32(q1v.y * qscale),
                f2tf32(q1v.z * qscale), f2tf32(q1v.w * qscale));
        }
    }

    float o[8][4];
#pragma unroll
    for (int nt = 0; nt < 8; nt++)
#pragma unroll
        for (int i = 0; i < 4; i++) o[nt][i] = 0.f;
    float m_a = -INFINITY, m_b = -INFINITY, l_a = 0.f, l_b = 0.f;

    const float* mrow_a = mask + ((long)b * SS + q0 + w * 16 + g) * SS;
    const float* mrow_b = mrow_a + 8L * SS;

    __syncthreads();

    for (int kb = 0; kb < SS / 64; kb++) {
        const int k0 = kb * 64;
        // stage K and V (V transposed)
        {
            const long kb0 = ((long)(b * SS + k0 + sr)) * DD + hoff + sc;
            const long kb1 = kb0 + 32L * DD;
#pragma unroll
            for (int i = 0; i < 16; i += 4) {
                float4 tk0 = *(const float4*)(K + kb0 + i);
                float4 tk1 = *(const float4*)(K + kb1 + i);
                *(float4*)&Ks[sr * APT + sc + i] = make_float4(
                    f2tf32(tk0.x), f2tf32(tk0.y), f2tf32(tk0.z), f2tf32(tk0.w));
                *(float4*)&Ks[(sr + 32) * APT + sc + i] = make_float4(
                    f2tf32(tk1.x), f2tf32(tk1.y), f2tf32(tk1.z), f2tf32(tk1.w));
                float4 tv0 = *(const float4*)(V + kb0 + i);
                float4 tv1 = *(const float4*)(V + kb1 + i);
                Vt[(sc + i + 0) * APT + sr] = f2tf32(tv0.x);
                Vt[(sc + i + 1) * APT + sr] = f2tf32(tv0.y);
                Vt[(sc + i + 2) * APT + sr] = f2tf32(tv0.z);
                Vt[(sc + i + 3) * APT + sr] = f2tf32(tv0.w);
                Vt[(sc + i + 0) * APT + sr + 32] = f2tf32(tv1.x);
                Vt[(sc + i + 1) * APT + sr + 32] = f2tf32(tv1.y);
                Vt[(sc + i + 2) * APT + sr + 32] = f2tf32(tv1.z);
                Vt[(sc + i + 3) * APT + sr + 32] = f2tf32(tv1.w);
            }
        }
        __syncthreads();

        // S = Qs @ Ks^T  (per warp: rows 16w..16w+15, all 64 cols)
        float s[8][4];
#pragma unroll
        for (int nt = 0; nt < 8; nt++)
#pragma unroll
            for (int i = 0; i < 4; i++) s[nt][i] = 0.f;
#pragma unroll
        for (int ks = 0; ks < 8; ks++) {
            const int rb = (w * 16 + g) * APT + ks * 8 + t;
            unsigned a0 = __float_as_uint(Qs[rb]);
            unsigned a1 = __float_as_uint(Qs[rb + 8 * APT]);
            unsigned a2 = __float_as_uint(Qs[rb + 4]);
            unsigned a3 = __float_as_uint(Qs[rb + 8 * APT + 4]);
#pragma unroll
            for (int nt = 0; nt < 8; nt++) {
                const int cb = (nt * 8 + g) * APT + ks * 8 + t;
                unsigned b0 = __float_as_uint(Ks[cb]);
                unsigned b1 = __float_as_uint(Ks[cb + 4]);
                mma_tf32(s[nt], a0, a1, a2, a3, b0, b1);
            }
        }

        // multiplicative mask, then streaming softmax (log2 domain)
        float mx_a = -INFINITY, mx_b = -INFINITY;
#pragma unroll
        for (int nt = 0; nt < 8; nt++) {
            const float2 ma = *(const float2*)(mrow_a + k0 + nt * 8 + 2 * t);
            const float2 mb = *(const float2*)(mrow_b + k0 + nt * 8 + 2 * t);
            s[nt][0] *= ma.x; s[nt][1] *= ma.y;
            s[nt][2] *= mb.x; s[nt][3] *= mb.y;
            mx_a = fmaxf(mx_a, fmaxf(s[nt][0], s[nt][1]));
            mx_b = fmaxf(mx_b, fmaxf(s[nt][2], s[nt][3]));
        }
        mx_a = fmaxf(mx_a, __shfl_xor_sync(0xffffffffu, mx_a, 1));
        mx_a = fmaxf(mx_a, __shfl_xor_sync(0xffffffffu, mx_a, 2));
        mx_b = fmaxf(mx_b, __shfl_xor_sync(0xffffffffu, mx_b, 1));
        mx_b = fmaxf(mx_b, __shfl_xor_sync(0xffffffffu, mx_b, 2));
        const float mn_a = fmaxf(m_a, mx_a), mn_b = fmaxf(m_b, mx_b);
        const float al_a = exp2f(m_a - mn_a), al_b = exp2f(m_b - mn_b);
        float sum_a = 0.f, sum_b = 0.f;
#pragma unroll
        for (int nt = 0; nt < 8; nt++) {
            const float p0 = exp2f(s[nt][0] - mn_a);
            const float p1 = exp2f(s[nt][1] - mn_a);
            const float p2 = exp2f(s[nt][2] - mn_b);
            const float p3 = exp2f(s[nt][3] - mn_b);
            sum_a += p0 + p1; sum_b += p2 + p3;
            const int pb = (w * 16 + g) * APT + nt * 8 + 2 * t;
            *(float2*)&Ps[pb] = make_float2(f2tf32(p0), f2tf32(p1));
            *(float2*)&Ps[pb + 8 * APT] = make_float2(f2tf32(p2), f2tf32(p3));
        }
        sum_a += __shfl_xor_sync(0xffffffffu, sum_a, 1);
        sum_a += __shfl_xor_sync(0xffffffffu, sum_a, 2);
        sum_b += __shfl_xor_sync(0xffffffffu, sum_b, 1);
        sum_b += __shfl_xor_sync(0xffffffffu, sum_b, 2);
        l_a = l_a * al_a + sum_a;
        l_b = l_b * al_b + sum_b;
        m_a = mn_a; m_b = mn_b;
#pragma unroll
        for (int nt = 0; nt < 8; nt++) {
            o[nt][0] *= al_a; o[nt][1] *= al_a;
            o[nt][2] *= al_b; o[nt][3] *= al_b;
        }
        __syncwarp();

        // O += P @ V   (A = Ps rows 16w.., B = Vt)
#pragma unroll
        for (int ks = 0; ks < 8; ks++) {
            const int rb = (w * 16 + g) * APT + ks * 8 + t;
            unsigned a0 = __float_as_uint(Ps[rb]);
            unsigned a1 = __float_as_uint(Ps[rb + 8 * APT]);
            unsigned a2 = __float_as_uint(Ps[rb + 4]);
            unsigned a3 = __float_as_uint(Ps[rb + 8 * APT + 4]);
#pragma unroll
            for (int nt = 0; nt < 8; nt++) {
                const int cb = (nt * 8 + g) * APT + ks * 8 + t;
                unsigned b0 = __float_as_uint(Vt[cb]);
                unsigned b1 = __float_as_uint(Vt[cb + 4]);
                mma_tf32(o[nt], a0, a1, a2, a3, b0, b1);
            }
        }
        __syncthreads();
    }

    // finalize + fused residual: x1 = x + O / l
    const float inv_a = 1.f / l_a, inv_b = 1.f / l_b;
    const long oa = ((long)(b * SS + q0 + w * 16 + g)) * DD + hoff;
    const long ob = oa + 8L * DD;
#pragma unroll
    for (int nt = 0; nt < 8; nt++) {
        const int c = nt * 8 + 2 * t;
        const float2 xa = *(const float2*)(x + oa + c);
        const float2 xb = *(const float2*)(x + ob + c);
        *(float2*)(x1 + oa + c) = make_float2(xa.x + o[nt][0] * inv_a,
                                              xa.y + o[nt][1] * inv_a);
        *(float2*)(x1 + ob + c) = make_float2(xb.x + o[nt][2] * inv_b,
                                              xb.y + o[nt][3] * inv_b);
    }
}

// ---------------------------------------------------------------------------
// Launch: LN1 -> Q/K/V GEMMs -> flash attn (+residual) -> LN2 -> FFN1(relu)
//         -> FFN2 (+bias +residual) -> d_out
// NOTE: reference never applies the output projection (wo/bo unused).
// ---------------------------------------------------------------------------
extern "C" void kernel_launch(void* const* d_in, const int* in_sizes, int n_in,
                              void* d_out, int out_size)
{
    const float* x    = (const float*)d_in[0];
    const float* mask = (const float*)d_in[1];
    const float* wq   = (const float*)d_in[2];
    const float* bq   = (const float*)d_in[3];
    const float* wk   = (const float*)d_in[4];
    const float* bk   = (const float*)d_in[5];
    const float* wv   = (const float*)d_in[6];
    const float* bv   = (const float*)d_in[7];
    // d_in[8]=wo, d_in[9]=bo unused by the reference forward
    const float* w1   = (const float*)d_in[10];
    const float* b1   = (const float*)d_in[11];
    const float* w2   = (const float*)d_in[12];
    const float* b2   = (const float*)d_in[13];
    const float* g1   = (const float*)d_in[14];
    const float* be1  = (const float*)d_in[15];
    const float* g2   = (const float*)d_in[16];
    const float* be2  = (const float*)d_in[17];
    float* out = (float*)d_out;

    float *l1, *qb, *kb, *vb, *x1, *l2, *hb;
    cudaGetSymbolAddress((void**)&l1, g_l1);
    cudaGetSymbolAddress((void**)&qb, g_q);
    cudaGetSymbolAddress((void**)&kb, g_k);
    cudaGetSymbolAddress((void**)&vb, g_v);
    cudaGetSymbolAddress((void**)&x1, g_x1);
    cudaGetSymbolAddress((void**)&l2, g_l2);
    cudaGetSymbolAddress((void**)&hb, g_hb);

    // LN1
    ln_kernel<<<MM, 256>>>(x, g1, be1, l1);

    // QKV projections (tf32 MMA)
    dim3 gproj(DD / 128, MM / 128);   // (6, 64)
    mma_gemm<0><<<gproj, 256>>>(l1, wq, bq, nullptr, qb, MM, DD, DD);
    mma_gemm<0><<<gproj, 256>>>(l1, wk, bk, nullptr, kb, MM, DD, DD);
    mma_gemm<0><<<gproj, 256>>>(l1, wv, bv, nullptr, vb, MM, DD, DD);

    // Flash attention + residual (tf32 MMA)
    cudaFuncSetAttribute(attn_mma_kernel, cudaFuncAttributeMaxDynamicSharedMemorySize, ATTN_SMEM);
    attn_mma_kernel<<<dim3(SS / 64, HH, BB), 128, ATTN_SMEM>>>(qb, kb, vb, mask, x, x1);

    // LN2
    ln_kernel<<<MM, 256>>>(x1, g2, be2, l2);

    // FFN (tf32 MMA)
    mma_gemm<1><<<dim3(DFF / 128, MM / 128), 256>>>(l2, w1, b1, nullptr, hb, MM, DFF, DD);
    mma_gemm<2><<<dim3(DD / 128, MM / 128), 256>>>(hb, w2, b2, x1, out, MM, DD, DFF);
}

// round 4
// speedup vs baseline: 4.2650x; 1.2631x over previous
#include <cuda_runtime.h>
#include <cuda_bf16.h>
#include <cstdint>
#include <math.h>

// Problem constants
#define BB 2
#define SS 4096
#define DD 768
#define HH 12
#define DHH 64
#define DFF 3072
#define MM (BB*SS)   // 8192

// ---------------------------------------------------------------------------
// Scratch (device globals — allocation-free per harness rules)
// ---------------------------------------------------------------------------
__device__ float g_l1[MM*DD];
__device__ float g_q [MM*DD];
__device__ float g_k [MM*DD];
__device__ float g_v [MM*DD];
__device__ float g_x1[MM*DD];
__device__ float g_l2[MM*DD];
__device__ float g_hb[MM*DFF];
// tf32-rounded weight copies (same layout as inputs, [K,N] row-major)
__device__ float g_wqr[DD*DD];
__device__ float g_wkr[DD*DD];
__device__ float g_wvr[DD*DD];
__device__ float g_w1r[DD*DFF];
__device__ float g_w2r[DFF*DD];

// ---------------------------------------------------------------------------
// Helpers
// ---------------------------------------------------------------------------
__device__ __forceinline__ float f2tf32(float x) {
    unsigned r;
    asm("cvt.rna.tf32.f32 %0, %1;" : "=r"(r) : "f"(x));
    return __uint_as_float(r);
}

__device__ __forceinline__ float ex2(float x) {
    float r;
    asm("ex2.approx.f32 %0, %1;" : "=f"(r) : "f"(x));
    return r;
}

__device__ __forceinline__ uint32_t smem_u32(const void* p) {
    uint32_t a;
    asm("{ .reg .u64 t; cvta.to.shared.u64 t, %1; cvt.u32.u64 %0, t; }"
        : "=r"(a) : "l"(p));
    return a;
}

#define CP_ASYNC16(dst, src) \
    asm volatile("cp.async.cg.shared.global [%0], [%1], 16;" :: "r"((uint32_t)(dst)), "l"(src) : "memory")
#define CP_ASYNC_COMMIT() asm volatile("cp.async.commit_group;" ::: "memory")
#define CP_ASYNC_WAIT(n)  asm volatile("cp.async.wait_group %0;" :: "n"(n) : "memory")

__device__ __forceinline__ void mma_tf32(float (&d)[4],
                                         unsigned a0, unsigned a1, unsigned a2, unsigned a3,
                                         unsigned b0, unsigned b1)
{
    asm volatile(
        "mma.sync.aligned.m16n8k8.row.col.f32.tf32.tf32.f32 "
        "{%0,%1,%2,%3}, {%4,%5,%6,%7}, {%8,%9}, {%0,%1,%2,%3};\n"
        : "+f"(d[0]), "+f"(d[1]), "+f"(d[2]), "+f"(d[3])
        : "r"(a0), "r"(a1), "r"(a2), "r"(a3), "r"(b0), "r"(b1));
}

// ---------------------------------------------------------------------------
// tf32 rounding pass for weights (vectorized grid-stride)
// ---------------------------------------------------------------------------
__global__ void round_kernel(const float* __restrict__ in, float* __restrict__ out, int n4)
{
    int i = blockIdx.x * blockDim.x + threadIdx.x;
    if (i < n4) {
        float4 v = ((const float4*)in)[i];
        ((float4*)out)[i] = make_float4(f2tf32(v.x), f2tf32(v.y), f2tf32(v.z), f2tf32(v.w));
    }
}

// ---------------------------------------------------------------------------
// LayerNorm: torch-style, unbiased std (ddof=1), normalizer = (sigma + eps).
// Output tf32-rounded (feeds GEMM A operands only).
// ---------------------------------------------------------------------------
__global__ void ln_kernel(const float* __restrict__ x,
                          const float* __restrict__ gamma,
                          const float* __restrict__ beta,
                          float* __restrict__ out)
{
    const int row = blockIdx.x;
    const float* xr = x + (long)row * DD;
    float* orow = out + (long)row * DD;

    float vals[3];
    float s = 0.f, ss = 0.f;
#pragma unroll
    for (int t = 0; t < 3; t++) {
        float v = xr[threadIdx.x + t * 256];
        vals[t] = v;
        s += v; ss += v * v;
    }
#pragma unroll
    for (int o = 16; o > 0; o >>= 1) {
        s  += __shfl_xor_sync(0xffffffffu, s,  o);
        ss += __shfl_xor_sync(0xffffffffu, ss, o);
    }
    __shared__ float sw[8], ssw[8];
    __shared__ float mu_s, inv_s;
    const int warp = threadIdx.x >> 5, lane = threadIdx.x & 31;
    if (lane == 0) { sw[warp] = s; ssw[warp] = ss; }
    __syncthreads();
    if (threadIdx.x == 0) {
        float ts = 0.f, tss = 0.f;
#pragma unroll
        for (int i = 0; i < 8; i++) { ts += sw[i]; tss += ssw[i]; }
        float mu  = ts / 768.f;
        float var = fmaxf((tss - 768.f * mu * mu) / 767.f, 0.f);
        mu_s  = mu;
        inv_s = 1.f / (sqrtf(var) + 1e-6f);
    }
    __syncthreads();
    const float mu = mu_s, inv = inv_s;
#pragma unroll
    for (int t = 0; t < 3; t++) {
        int c = threadIdx.x + t * 256;
        orow[c] = f2tf32(gamma[c] * (vals[t] - mu) * inv + beta[c]);
    }
}

// ---------------------------------------------------------------------------
// TF32 tensor-core GEMM, cp.async 2-stage pipeline.
// C[M,N] = A[M,K] @ B[K,N] + bias, block tile 128x128, BK=16,
// 256 threads = 8 warps (2x4), warp tile 64x32, mma.sync.m16n8k8.
// A and B must already be tf32-rounded in global memory.
// EPI: 1 = bias+relu+round, 2 = bias+residual, 3 = bias+round
// ---------------------------------------------------------------------------
#define AP 20    // As pitch: frag banks (4g + t) distinct -> conflict-free
#define BP 136   // Bs pitch: frag banks (8t + g) distinct -> conflict-free

template<int EPI>
__global__ __launch_bounds__(256)
void mma_gemm(const float* __restrict__ A, const float* __restrict__ Bm,
              const float* __restrict__ bias, const float* __restrict__ res,
              float* __restrict__ C, int M, int N, int Kdim)
{
    __shared__ float As[2][128 * AP];
    __shared__ float Bs[2][16 * BP];

    const int tid  = threadIdx.x;
    const int wid  = tid >> 5, lane = tid & 31;
    const int wm   = wid >> 2, wn = wid & 3;
    const int g    = lane >> 2, t = lane & 3;
    const int row0 = blockIdx.y * 128, col0 = blockIdx.x * 128;

    const int ar = tid >> 1, ac = (tid & 1) * 8;
    const int br = tid >> 4, bc = (tid & 15) * 8;

    const float* Aptr = A  + (long)(row0 + ar) * Kdim + ac;
    const float* Bptr = Bm + (long)br * N + col0 + bc;

    const uint32_t asb = smem_u32(&As[0][0]);
    const uint32_t bsb = smem_u32(&Bs[0][0]);
    const uint32_t adst = asb + (ar * AP + ac) * 4;
    const uint32_t bdst = bsb + (br * BP + bc) * 4;

    float acc[4][4][4];
#pragma unroll
    for (int i = 0; i < 4; i++)
#pragma unroll
        for (int j = 0; j < 4; j++)
#pragma unroll
            for (int k = 0; k < 4; k++) acc[i][j][k] = 0.f;

    const int niter = Kdim / 16;

    // prologue: stage 0
    CP_ASYNC16(adst, Aptr);
    CP_ASYNC16(adst + 16, Aptr + 4);
    CP_ASYNC16(bdst, Bptr);
    CP_ASYNC16(bdst + 16, Bptr + 4);
    CP_ASYNC_COMMIT();

    for (int it = 0; it < niter; it++) {
        const int buf = it & 1;
        if (it + 1 < niter) {
            const int nb = (it + 1) & 1;
            const long ka = (long)(it + 1) * 16;
            const uint32_t ad = adst + nb * (128 * AP * 4);
            const uint32_t bd = bdst + nb * (16 * BP * 4);
            CP_ASYNC16(ad, Aptr + ka);
            CP_ASYNC16(ad + 16, Aptr + ka + 4);
            CP_ASYNC16(bd, Bptr + ka * N);
            CP_ASYNC16(bd + 16, Bptr + ka * N + 4);
            CP_ASYNC_COMMIT();
            CP_ASYNC_WAIT(1);
        } else {
            CP_ASYNC_WAIT(0);
        }
        __syncthreads();

        const float* as = As[buf];
        const float* bs = Bs[buf];
#pragma unroll
        for (int ks = 0; ks < 2; ks++) {
            unsigned af[4][4];
#pragma unroll
            for (int mt = 0; mt < 4; mt++) {
                const int rb = (wm * 64 + mt * 16 + g) * AP + ks * 8 + t;
                af[mt][0] = __float_as_uint(as[rb]);
                af[mt][1] = __float_as_uint(as[rb + 8 * AP]);
                af[mt][2] = __float_as_uint(as[rb + 4]);
                af[mt][3] = __float_as_uint(as[rb + 8 * AP + 4]);
            }
            unsigned bf[4][2];
#pragma unroll
            for (int nt = 0; nt < 4; nt++) {
                const int cb = (ks * 8 + t) * BP + wn * 32 + nt * 8 + g;
                bf[nt][0] = __float_as_uint(bs[cb]);
                bf[nt][1] = __float_as_uint(bs[cb + 4 * BP]);
            }
#pragma unroll
            for (int mt = 0; mt < 4; mt++)
#pragma unroll
                for (int nt = 0; nt < 4; nt++)
                    mma_tf32(acc[mt][nt], af[mt][0], af[mt][1], af[mt][2], af[mt][3],
                             bf[nt][0], bf[nt][1]);
        }
        __syncthreads();
    }

    // epilogue
#pragma unroll
    for (int mt = 0; mt < 4; mt++) {
#pragma unroll
        for (int nt = 0; nt < 4; nt++) {
            const int  ccol = col0 + wn * 32 + nt * 8 + 2 * t;
            const long ra   = row0 + wm * 64 + mt * 16 + g;
            const long rb2  = ra + 8;
            const float bx = bias[ccol], by = bias[ccol + 1];
            float v0 = acc[mt][nt][0] + bx;
            float v1 = acc[mt][nt][1] + by;
            float v2 = acc[mt][nt][2] + bx;
            float v3 = acc[mt][nt][3] + by;
            if (EPI == 1) {
                v0 = f2tf32(fmaxf(v0, 0.f)); v1 = f2tf32(fmaxf(v1, 0.f));
                v2 = f2tf32(fmaxf(v2, 0.f)); v3 = f2tf32(fmaxf(v3, 0.f));
            }
            if (EPI == 3) {
                v0 = f2tf32(v0); v1 = f2tf32(v1);
                v2 = f2tf32(v2); v3 = f2tf32(v3);
            }
            if (EPI == 2) {
                const float2 r0 = *(const float2*)(res + ra  * N + ccol);
                const float2 r1 = *(const float2*)(res + rb2 * N + ccol);
                v0 += r0.x; v1 += r0.y; v2 += r1.x; v3 += r1.y;
            }
            *(float2*)(C + ra  * N + ccol) = make_float2(v0, v1);
            *(float2*)(C + rb2 * N + ccol) = make_float2(v2, v3);
        }
    }
}

// ---------------------------------------------------------------------------
// Flash attention, tf32 mma.sync. Q-tile 128 rows, k-tile 64, 256 threads
// (8 warps; warp w owns q rows 16w..16w+15). K staged via cp.async
// (Q/K/V pre-rounded to tf32 by the QKV GEMM epilogue). V transposed at
// staging. Grid x = head (fastest) so the 12 heads sharing a mask slice run
// concurrently -> mask L2 reuse. Fuses residual: x1 = x + ctx.
// ---------------------------------------------------------------------------
#define PT 68    // smem pitch: frag banks (4g + t) distinct
#define QT 128
#define KT 64
#define ATTN_SMEM ((QT + KT + KT + QT) * PT * (int)sizeof(float))   // 104448

__global__ __launch_bounds__(256)
void attn_mma_kernel(const float* __restrict__ Q, const float* __restrict__ K,
                     const float* __restrict__ V, const float* __restrict__ mask,
                     const float* __restrict__ x, float* __restrict__ x1)
{
    extern __shared__ float sm[];
    float* Qs = sm;                       // [128][PT]
    float* Ks = sm + QT * PT;             // [64][PT]
    float* Vt = sm + (QT + KT) * PT;      // [64][PT] transposed: Vt[d][key]
    float* Ps = sm + (QT + 2 * KT) * PT;  // [128][PT]

    const int tid = threadIdx.x;
    const int w = tid >> 5, lane = tid & 31;
    const int g = lane >> 2, t = lane & 3;
    const int h = blockIdx.x, qb = blockIdx.y, b = blockIdx.z;
    const int q0 = qb * QT, hoff = h * DHH;

    const float qscale = 0.125f * 1.4426950408889634f;  // 1/sqrt(64)*log2(e)

    // stage Q (scaled + rounded): row = tid>>1 (0..127), half-row (tid&1)*32
    {
        const int sr = tid >> 1, sc0 = (tid & 1) * 32;
        const float* qsrc = Q + ((long)(b * SS + q0 + sr)) * DD + hoff + sc0;
        float* qdst = &Qs[sr * PT + sc0];
#pragma unroll
        for (int i = 0; i < 32; i += 4) {
            float4 v = *(const float4*)(qsrc + i);
            *(float4*)(qdst + i) = make_float4(
                f2tf32(v.x * qscale), f2tf32(v.y * qscale),
                f2tf32(v.z * qscale), f2tf32(v.w * qscale));
        }
    }

    float o[8][4];
#pragma unroll
    for (int nt = 0; nt < 8; nt++)
#pragma unroll
        for (int i = 0; i < 4; i++) o[nt][i] = 0.f;
    float m_a = -INFINITY, m_b = -INFINITY, l_a = 0.f, l_b = 0.f;

    const float* mrow_a = mask + ((long)b * SS + q0 + w * 16 + g) * SS;
    const float* mrow_b = mrow_a + 8L * SS;

    // K/V staging mapping: row kr = tid>>2 (0..63), cols kc..kc+15
    const int kr = tid >> 2, kc = (tid & 3) * 16;
    const uint32_t ksdst = smem_u32(Ks) + (kr * PT + kc) * 4;

    __syncthreads();

    for (int kb = 0; kb < SS / KT; kb++) {
        const int k0 = kb * KT;
        const long kvsrc = ((long)(b * SS + k0 + kr)) * DD + hoff + kc;

        // K via cp.async (already tf32-rounded)
#pragma unroll
        for (int j = 0; j < 4; j++)
            CP_ASYNC16(ksdst + j * 16, K + kvsrc + j * 4);
        CP_ASYNC_COMMIT();

        // V transpose through registers (already rounded, no cvt)
#pragma unroll
        for (int j = 0; j < 4; j++) {
            float4 v = *(const float4*)(V + kvsrc + j * 4);
            Vt[(kc + j * 4 + 0) * PT + kr] = v.x;
            Vt[(kc + j * 4 + 1) * PT + kr] = v.y;
            Vt[(kc + j * 4 + 2) * PT + kr] = v.z;
            Vt[(kc + j * 4 + 3) * PT + kr] = v.w;
        }
        CP_ASYNC_WAIT(0);
        __syncthreads();

        // S = Qs @ Ks^T (per warp: 16 q rows x 64 k cols)
        float s[8][4];
#pragma unroll
        for (int nt = 0; nt < 8; nt++)
#pragma unroll
            for (int i = 0; i < 4; i++) s[nt][i] = 0.f;
#pragma unroll
        for (int ks = 0; ks < 8; ks++) {
            const int rb = (w * 16 + g) * PT + ks * 8 + t;
            unsigned a0 = __float_as_uint(Qs[rb]);
            unsigned a1 = __float_as_uint(Qs[rb + 8 * PT]);
            unsigned a2 = __float_as_uint(Qs[rb + 4]);
            unsigned a3 = __float_as_uint(Qs[rb + 8 * PT + 4]);
#pragma unroll
            for (int nt = 0; nt < 8; nt++) {
                const int cb = (nt * 8 + g) * PT + ks * 8 + t;
                unsigned b0 = __float_as_uint(Ks[cb]);
                unsigned b1 = __float_as_uint(Ks[cb + 4]);
                mma_tf32(s[nt], a0, a1, a2, a3, b0, b1);
            }
        }

        // multiplicative mask then streaming softmax (log2 domain)
        float mx_a = -INFINITY, mx_b = -INFINITY;
#pragma unroll
        for (int nt = 0; nt < 8; nt++) {
            const float2 ma = *(const float2*)(mrow_a + k0 + nt * 8 + 2 * t);
            const float2 mb = *(const float2*)(mrow_b + k0 + nt * 8 + 2 * t);
            s[nt][0] *= ma.x; s[nt][1] *= ma.y;
            s[nt][2] *= mb.x; s[nt][3] *= mb.y;
            mx_a = fmaxf(mx_a, fmaxf(s[nt][0], s[nt][1]));
            mx_b = fmaxf(mx_b, fmaxf(s[nt][2], s[nt][3]));
        }
        mx_a = fmaxf(mx_a, __shfl_xor_sync(0xffffffffu, mx_a, 1));
        mx_a = fmaxf(mx_a, __shfl_xor_sync(0xffffffffu, mx_a, 2));
        mx_b = fmaxf(mx_b, __shfl_xor_sync(0xffffffffu, mx_b, 1));
        mx_b = fmaxf(mx_b, __shfl_xor_sync(0xffffffffu, mx_b, 2));
        const float mn_a = fmaxf(m_a, mx_a), mn_b = fmaxf(m_b, mx_b);
        const float al_a = ex2(m_a - mn_a), al_b = ex2(m_b - mn_b);
        float sum_a = 0.f, sum_b = 0.f;
#pragma unroll
        for (int nt = 0; nt < 8; nt++) {
            const float p0 = ex2(s[nt][0] - mn_a);
            const float p1 = ex2(s[nt][1] - mn_a);
            const float p2 = ex2(s[nt][2] - mn_b);
            const float p3 = ex2(s[nt][3] - mn_b);
            sum_a += p0 + p1; sum_b += p2 + p3;
            const int pb = (w * 16 + g) * PT + nt * 8 + 2 * t;
            *(float2*)&Ps[pb] = make_float2(f2tf32(p0), f2tf32(p1));
            *(float2*)&Ps[pb + 8 * PT] = make_float2(f2tf32(p2), f2tf32(p3));
        }
        sum_a += __shfl_xor_sync(0xffffffffu, sum_a, 1);
        sum_a += __shfl_xor_sync(0xffffffffu, sum_a, 2);
        sum_b += __shfl_xor_sync(0xffffffffu, sum_b, 1);
        sum_b += __shfl_xor_sync(0xffffffffu, sum_b, 2);
        l_a = l_a * al_a + sum_a;
        l_b = l_b * al_b + sum_b;
        m_a = mn_a; m_b = mn_b;
#pragma unroll
        for (int nt = 0; nt < 8; nt++) {
            o[nt][0] *= al_a; o[nt][1] *= al_a;
            o[nt][2] *= al_b; o[nt][3] *= al_b;
        }
        __syncwarp();

        // O += P @ V
#pragma unroll
        for (int ks = 0; ks < 8; ks++) {
            const int rb = (w * 16 + g) * PT + ks * 8 + t;
            unsigned a0 = __float_as_uint(Ps[rb]);
            unsigned a1 = __float_as_uint(Ps[rb + 8 * PT]);
            unsigned a2 = __float_as_uint(Ps[rb + 4]);
            unsigned a3 = __float_as_uint(Ps[rb + 8 * PT + 4]);
#pragma unroll
            for (int nt = 0; nt < 8; nt++) {
                const int cb = (nt * 8 + g) * PT + ks * 8 + t;
                unsigned b0 = __float_as_uint(Vt[cb]);
                unsigned b1 = __float_as_uint(Vt[cb + 4]);
                mma_tf32(o[nt], a0, a1, a2, a3, b0, b1);
            }
        }
        __syncthreads();
    }

    // finalize + fused residual: x1 = x + O / l
    const float inv_a = 1.f / l_a, inv_b = 1.f / l_b;
    const long oa = ((long)(b * SS + q0 + w * 16 + g)) * DD + hoff;
    const long ob = oa + 8L * DD;
#pragma unroll
    for (int nt = 0; nt < 8; nt++) {
        const int c = nt * 8 + 2 * t;
        const float2 xa = *(const float2*)(x + oa + c);
        const float2 xb = *(const float2*)(x + ob + c);
        *(float2*)(x1 + oa + c) = make_float2(xa.x + o[nt][0] * inv_a,
                                              xa.y + o[nt][1] * inv_a);
        *(float2*)(x1 + ob + c) = make_float2(xb.x + o[nt][2] * inv_b,
                                              xb.y + o[nt][3] * inv_b);
    }
}

// ---------------------------------------------------------------------------
// Launch
// ---------------------------------------------------------------------------
extern "C" void kernel_launch(void* const* d_in, const int* in_sizes, int n_in,
                              void* d_out, int out_size)
{
    const float* x    = (const float*)d_in[0];
    const float* mask = (const float*)d_in[1];
    const float* wq   = (const float*)d_in[2];
    const float* bq   = (const float*)d_in[3];
    const float* wk   = (const float*)d_in[4];
    const float* bk   = (const float*)d_in[5];
    const float* wv   = (const float*)d_in[6];
    const float* bv   = (const float*)d_in[7];
    // d_in[8]=wo, d_in[9]=bo unused by the reference forward
    const float* w1   = (const float*)d_in[10];
    const float* b1   = (const float*)d_in[11];
    const float* w2   = (const float*)d_in[12];
    const float* b2   = (const float*)d_in[13];
    const float* g1   = (const float*)d_in[14];
    const float* be1  = (const float*)d_in[15];
    const float* g2   = (const float*)d_in[16];
    const float* be2  = (const float*)d_in[17];
    float* out = (float*)d_out;

    float *l1, *qb_, *kb_, *vb_, *x1, *l2, *hb;
    float *wqr, *wkr, *wvr, *w1r, *w2r;
    cudaGetSymbolAddress((void**)&l1, g_l1);
    cudaGetSymbolAddress((void**)&qb_, g_q);
    cudaGetSymbolAddress((void**)&kb_, g_k);
    cudaGetSymbolAddress((void**)&vb_, g_v);
    cudaGetSymbolAddress((void**)&x1, g_x1);
    cudaGetSymbolAddress((void**)&l2, g_l2);
    cudaGetSymbolAddress((void**)&hb, g_hb);
    cudaGetSymbolAddress((void**)&wqr, g_wqr);
    cudaGetSymbolAddress((void**)&wkr, g_wkr);
    cudaGetSymbolAddress((void**)&wvr, g_wvr);
    cudaGetSymbolAddress((void**)&w1r, g_w1r);
    cudaGetSymbolAddress((void**)&w2r, g_w2r);

    cudaFuncSetAttribute(attn_mma_kernel, cudaFuncAttributeMaxDynamicSharedMemorySize, ATTN_SMEM);

    // tf32-round the weights once (layout unchanged)
    const int ndd4  = DD * DD / 4;
    const int nff4  = DD * DFF / 4;
    round_kernel<<<(ndd4 + 255) / 256, 256>>>(wq, wqr, ndd4);
    round_kernel<<<(ndd4 + 255) / 256, 256>>>(wk, wkr, ndd4);
    round_kernel<<<(ndd4 + 255) / 256, 256>>>(wv, wvr, ndd4);
    round_kernel<<<(nff4 + 255) / 256, 256>>>(w1, w1r, nff4);
    round_kernel<<<(nff4 + 255) / 256, 256>>>(w2, w2r, nff4);

    // LN1 (rounds output)
    ln_kernel<<<MM, 256>>>(x, g1, be1, l1);

    // QKV projections (EPI=3: bias + tf32 round, so attention can stage raw)
    dim3 gproj(DD / 128, MM / 128);   // (6, 64)
    mma_gemm<3><<<gproj, 256>>>(l1, wqr, bq, nullptr, qb_, MM, DD, DD);
    mma_gemm<3><<<gproj, 256>>>(l1, wkr, bk, nullptr, kb_, MM, DD, DD);
    mma_gemm<3><<<gproj, 256>>>(l1, wvr, bv, nullptr, vb_, MM, DD, DD);

    // Flash attention + residual; head = fastest grid dim for mask L2 reuse
    attn_mma_kernel<<<dim3(HH, SS / QT, BB), 256, ATTN_SMEM>>>(qb_, kb_, vb_, mask, x, x1);

    // LN2 (rounds output)
    ln_kernel<<<MM, 256>>>(x1, g2, be2, l2);

    // FFN
    mma_gemm<1><<<dim3(DFF / 128, MM / 128), 256>>>(l2, w1r, b1, nullptr, hb, MM, DFF, DD);
    mma_gemm<2><<<dim3(DD / 128, MM / 128), 256>>>(hb, w2r, b2, x1, out, MM, DD, DFF);
}